// round 8
// baseline (speedup 1.0000x reference)
#include <cuda_runtime.h>
#include <cuda_bf16.h>
#include <cuda_fp16.h>
#include <stdint.h>

#define NN 50000
#define EE 800000
#define GG 500
#define H 128
#define OUTC 10
#define KS 136                 // padded row stride in f16 elems
#define SB 272                 // row stride bytes
#define IMG (128 * KS * 2)     // 34816 B per 128x128 f16 image
#define DSM (3 * IMG)          // 104448 B dynamic smem: A16, WH, WL

// ---------------- device scratch ----------------
__device__ __align__(16) __half g_hf0[NN * H];  // node features ping
__device__ __align__(16) __half g_hf1[NN * H];  // node features pong
__device__ int   g_deg[NN];
__device__ int   g_off[NN + 1];
__device__ int   g_cursor[NN];
__device__ int   g_srcs[EE];
__device__ float g_pool[GG * H];
__device__ float g_cnt[GG];
__device__ __align__(16) __half g_wh[6 * 128 * KS];  // weight images (Wt[n][k]) f16 hi
__device__ __align__(16) __half g_wl[6 * 128 * KS];  // f16 lo (residual)

// ---------------- PTX helpers (base ISA only) ----------------
__device__ __forceinline__ uint32_t smem_u32(const void* p) {
    uint32_t a;
    asm("{ .reg .u64 t; cvta.to.shared.u64 t, %1; cvt.u32.u64 %0, t; }" : "=r"(a) : "l"(p));
    return a;
}
#define LDSM4(r0, r1, r2, r3, addr) \
    asm volatile("ldmatrix.sync.aligned.m8n8.x4.shared.b16 {%0,%1,%2,%3}, [%4];" \
                 : "=r"(r0), "=r"(r1), "=r"(r2), "=r"(r3) : "r"(addr))
#define MMA16816(d, a0, a1, a2, a3, b0, b1) \
    asm volatile("mma.sync.aligned.m16n8k16.row.col.f32.f16.f16.f32 " \
                 "{%0,%1,%2,%3}, {%4,%5,%6,%7}, {%8,%9}, {%0,%1,%2,%3};" \
                 : "+f"((d)[0]), "+f"((d)[1]), "+f"((d)[2]), "+f"((d)[3]) \
                 : "r"(a0), "r"(a1), "r"(a2), "r"(a3), "r"(b0), "r"(b1))

// ---------------- setup: zero + counts ----------------
__global__ void zero_kernel(int n) {
    int i = blockIdx.x * blockDim.x + threadIdx.x;
    if (i < n) g_deg[i] = 0;
    if (i < GG * H) g_pool[i] = 0.f;
    if (i < GG) g_cnt[i] = 0.f;
}
__global__ void count_kernel(const int* __restrict__ dst, const int* __restrict__ batch,
                             int e, int n) {
    int i = blockIdx.x * blockDim.x + threadIdx.x;
    if (i < e) atomicAdd(&g_deg[dst[i]], 1);
    if (i < n) atomicAdd(&g_cnt[batch[i]], 1.0f);
}
__global__ void scan_kernel(int n) {
    __shared__ int part[1024];
    int t = threadIdx.x;
    int chunk = (n + 1023) >> 10;
    int start = t * chunk;
    int s = 0;
    for (int i = 0; i < chunk; i++) {
        int idx = start + i;
        if (idx < n) s += g_deg[idx];
    }
    part[t] = s;
    __syncthreads();
    for (int off = 1; off < 1024; off <<= 1) {
        int v = 0;
        if (t >= off) v = part[t - off];
        __syncthreads();
        part[t] += v;
        __syncthreads();
    }
    int base = (t == 0) ? 0 : part[t - 1];
    for (int i = 0; i < chunk; i++) {
        int idx = start + i;
        if (idx < n) {
            g_off[idx] = base;
            g_cursor[idx] = base;
            base += g_deg[idx];
        }
    }
    if (t == 1023) g_off[n] = part[1023];
}
__global__ void fill_kernel(const int* __restrict__ src, const int* __restrict__ dst, int e) {
    int i = blockIdx.x * blockDim.x + threadIdx.x;
    if (i < e) {
        int d = dst[i];
        int p = atomicAdd(&g_cursor[d], 1);
        g_srcs[p] = src[i];
    }
}

// ---------------- x -> f16 convert ----------------
__global__ void xconv_kernel(const float* __restrict__ x, int total4) {
    int i = blockIdx.x * blockDim.x + threadIdx.x;
    if (i < total4) {
        float4 v = ((const float4*)x)[i];
        __half2 h0 = __floats2half2_rn(v.x, v.y);
        __half2 h1 = __floats2half2_rn(v.z, v.w);
        uint2 o;
        o.x = *(unsigned int*)&h0;
        o.y = *(unsigned int*)&h1;
        ((uint2*)g_hf0)[i] = o;
    }
}

// ---------------- weight prep: Wt[n][k] f16 hi/lo, padded stride ----------------
__global__ void wprep_kernel(const float* __restrict__ c1W1, const float* __restrict__ c1W2,
                             const float* __restrict__ Ws1, const float* __restrict__ Ws2) {
    int m = blockIdx.x >> 2;
    int rg = blockIdx.x & 3;
    const float* W;
    if (m == 0) W = c1W1;
    else if (m == 1) W = c1W2;
    else {
        int l = (m - 2) >> 1;
        W = ((m & 1) == 0) ? (Ws1 + l * H * H) : (Ws2 + l * H * H);
    }
    int tid = threadIdx.x;
    int nrow = rg * 32 + (tid >> 3);
    int kb = (tid & 7) * 16;
    __half* oh = g_wh + m * 128 * KS;
    __half* ol = g_wl + m * 128 * KS;
#pragma unroll
    for (int i = 0; i < 8; i++) {
        int k = kb + 2 * i;
        float v0 = W[k * H + nrow];
        float v1 = W[(k + 1) * H + nrow];
        __half2 h2 = __floats2half2_rn(v0, v1);
        float2 hf = __half22float2(h2);
        __half2 l2 = __floats2half2_rn(v0 - hf.x, v1 - hf.y);
        *(__half2*)(oh + nrow * KS + k) = h2;
        *(__half2*)(ol + nrow * KS + k) = l2;
    }
}

// ---------------- fused agg + MLP on mma.sync ----------------
__device__ __forceinline__ void copy_w(char* WH, char* WL, int wi, int tid) {
    const uint4* s1 = (const uint4*)(g_wh + (size_t)wi * 128 * KS);
    const uint4* s2 = (const uint4*)(g_wl + (size_t)wi * 128 * KS);
    uint4* d1 = (uint4*)WH;
    uint4* d2 = (uint4*)WL;
    for (int j = tid; j < IMG / 16; j += 256) {
        d1[j] = s1[j];
        d2[j] = s2[j];
    }
}

__global__ __launch_bounds__(256, 2) void mlp_mma_kernel(
    const __half* __restrict__ hin, __half* __restrict__ hout,
    int w1i, int w2i,
    const float* __restrict__ b1, const float* __restrict__ b2,
    const float* __restrict__ gam, const float* __restrict__ bet,
    const float* __restrict__ rm, const float* __restrict__ rv,
    const float* __restrict__ eps,
    const int* __restrict__ batchv, int lastlayer, int n) {
    extern __shared__ char dsm[];
    __shared__ float s_b1[H], s_b2[H], s_sc[H], s_sf[H];

    char* A16 = dsm;
    char* WH = dsm + 1 * IMG;
    char* WL = dsm + 2 * IMG;

    int tid = threadIdx.x, wid = tid >> 5, lane = tid & 31;
    int wm = wid >> 1, wn = wid & 1;        // 4x2 warp grid; warp tile 32(m) x 64(n)
    int qg = lane >> 2, qt = lane & 3;      // quad group / thread

    if (tid < H) {
        s_b1[tid] = b1[tid];
        s_b2[tid] = b2[tid];
        float sc = gam[tid] * rsqrtf(rv[tid] + 1e-5f);
        s_sc[tid] = sc;
        s_sf[tid] = bet[tid] - rm[tid] * sc;
    }
    copy_w(WH, WL, w1i, tid);

    // fused aggregation: gather neighbor sums for this CTA's 128 rows -> A16 image
    // reads ONLY hin (written by the previous kernel launch) — no intra-grid race
    int row0 = blockIdx.x * 128;
    {
        float e = 1.0f + *eps;
        const uint2* in2 = (const uint2*)hin;
#pragma unroll 1
        for (int rr = 0; rr < 16; rr++) {
            int r = wid * 16 + rr;
            int grow = row0 + r;
            uint2* drow = (uint2*)(A16 + r * SB + lane * 8);
            if (grow < n) {
                uint2 sv = in2[(size_t)grow * 32 + lane];
                float2 f01 = __half22float2(*(__half2*)&sv.x);
                float2 f23 = __half22float2(*(__half2*)&sv.y);
                float ax = f01.x * e, ay = f01.y * e, az = f23.x * e, aw = f23.y * e;
                int s0 = g_off[grow], s1 = g_off[grow + 1];
                int i = s0;
                for (; i + 3 < s1; i += 4) {
                    uint2 va = in2[(size_t)g_srcs[i] * 32 + lane];
                    uint2 vb = in2[(size_t)g_srcs[i + 1] * 32 + lane];
                    uint2 vc = in2[(size_t)g_srcs[i + 2] * 32 + lane];
                    uint2 vd = in2[(size_t)g_srcs[i + 3] * 32 + lane];
                    float2 a01 = __half22float2(*(__half2*)&va.x);
                    float2 a23 = __half22float2(*(__half2*)&va.y);
                    float2 b01 = __half22float2(*(__half2*)&vb.x);
                    float2 b23 = __half22float2(*(__half2*)&vb.y);
                    float2 c01 = __half22float2(*(__half2*)&vc.x);
                    float2 c23 = __half22float2(*(__half2*)&vc.y);
                    float2 d01 = __half22float2(*(__half2*)&vd.x);
                    float2 d23 = __half22float2(*(__half2*)&vd.y);
                    ax += (a01.x + b01.x) + (c01.x + d01.x);
                    ay += (a01.y + b01.y) + (c01.y + d01.y);
                    az += (a23.x + b23.x) + (c23.x + d23.x);
                    aw += (a23.y + b23.y) + (c23.y + d23.y);
                }
                for (; i < s1; i++) {
                    uint2 va = in2[(size_t)g_srcs[i] * 32 + lane];
                    float2 a01 = __half22float2(*(__half2*)&va.x);
                    float2 a23 = __half22float2(*(__half2*)&va.y);
                    ax += a01.x; ay += a01.y; az += a23.x; aw += a23.y;
                }
                __half2 o0 = __floats2half2_rn(ax, ay);
                __half2 o1 = __floats2half2_rn(az, aw);
                uint2 o;
                o.x = *(unsigned int*)&o0;
                o.y = *(unsigned int*)&o1;
                *drow = o;
            } else {
                *drow = make_uint2(0, 0);
            }
        }
    }
    __syncthreads();

    // per-lane ldmatrix address offsets
    uint32_t aA16 = smem_u32(A16);
    uint32_t aWH = smem_u32(WH), aWL = smem_u32(WL);
    uint32_t a_loff = (uint32_t)((wm * 32 + (lane & 15)) * SB + (lane >> 4) * 16);
    uint32_t b_row = (uint32_t)((lane & 7) | ((lane & 16) >> 1));
    uint32_t b_loff = (uint32_t)((wn * 64) * SB) + b_row * SB + (((uint32_t)lane >> 3) & 1) * 16;

    float acc[2][8][4];

    for (int pass = 0; pass < 2; pass++) {
#pragma unroll
        for (int mf = 0; mf < 2; mf++)
#pragma unroll
            for (int nf = 0; nf < 8; nf++)
#pragma unroll
                for (int q = 0; q < 4; q++) acc[mf][nf][q] = 0.f;

#pragma unroll
        for (int ks = 0; ks < 8; ks++) {
            uint32_t a0, a1, a2, a3, a4, a5, a6, a7;
            uint32_t abase = aA16 + a_loff + (uint32_t)(ks * 32);
            LDSM4(a0, a1, a2, a3, abase);
            LDSM4(a4, a5, a6, a7, abase + 16u * SB);
#pragma unroll
            for (int prod = 0; prod < 2; prod++) {
                uint32_t wb = prod ? aWL : aWH;
#pragma unroll
                for (int g2 = 0; g2 < 4; g2++) {
                    uint32_t b0, b1x, b2, b3;
                    uint32_t bbase = wb + b_loff + (uint32_t)(g2 * 16 * SB + ks * 32);
                    LDSM4(b0, b1x, b2, b3, bbase);
                    MMA16816(acc[0][2 * g2],     a0, a1, a2, a3, b0, b1x);
                    MMA16816(acc[0][2 * g2 + 1], a0, a1, a2, a3, b2, b3);
                    MMA16816(acc[1][2 * g2],     a4, a5, a6, a7, b0, b1x);
                    MMA16816(acc[1][2 * g2 + 1], a4, a5, a6, a7, b2, b3);
                }
            }
        }

        if (pass == 0) {
            // all pass-0 reads of A16/WH/WL done
            __syncthreads();
            // epilogue 1: bias + relu -> rebuild A image (f16); also stage W2
#pragma unroll
            for (int mf = 0; mf < 2; mf++) {
                int rA = wm * 32 + mf * 16 + qg;
#pragma unroll
                for (int nf = 0; nf < 8; nf++) {
                    int c = wn * 64 + nf * 8 + 2 * qt;
                    float v0 = fmaxf(acc[mf][nf][0] + s_b1[c], 0.f);
                    float v1 = fmaxf(acc[mf][nf][1] + s_b1[c + 1], 0.f);
                    float v2 = fmaxf(acc[mf][nf][2] + s_b1[c], 0.f);
                    float v3 = fmaxf(acc[mf][nf][3] + s_b1[c + 1], 0.f);
                    *(__half2*)(A16 + rA * SB + c * 2)       = __floats2half2_rn(v0, v1);
                    *(__half2*)(A16 + (rA + 8) * SB + c * 2) = __floats2half2_rn(v2, v3);
                }
            }
            copy_w(WH, WL, w2i, tid);
            __syncthreads();
        }
    }

    // epilogue 2: bias + relu + BN -> hout f16 (or atomic pool on last layer)
#pragma unroll
    for (int mf = 0; mf < 2; mf++) {
        int rA = wm * 32 + mf * 16 + qg;
        int growA = row0 + rA, growB = growA + 8;
#pragma unroll
        for (int nf = 0; nf < 8; nf++) {
            int c = wn * 64 + nf * 8 + 2 * qt;
            float o0 = fmaxf(acc[mf][nf][0] + s_b2[c], 0.f)     * s_sc[c]     + s_sf[c];
            float o1 = fmaxf(acc[mf][nf][1] + s_b2[c + 1], 0.f) * s_sc[c + 1] + s_sf[c + 1];
            float o2 = fmaxf(acc[mf][nf][2] + s_b2[c], 0.f)     * s_sc[c]     + s_sf[c];
            float o3 = fmaxf(acc[mf][nf][3] + s_b2[c + 1], 0.f) * s_sc[c + 1] + s_sf[c + 1];
            if (!lastlayer) {
                if (growA < n) *(__half2*)&hout[(size_t)growA * H + c] = __floats2half2_rn(o0, o1);
                if (growB < n) *(__half2*)&hout[(size_t)growB * H + c] = __floats2half2_rn(o2, o3);
            } else {
                if (growA < n) {
                    float* pp = g_pool + (size_t)batchv[growA] * H + c;
                    atomicAdd(pp, o0);
                    atomicAdd(pp + 1, o1);
                }
                if (growB < n) {
                    float* pp = g_pool + (size_t)batchv[growB] * H + c;
                    atomicAdd(pp, o2);
                    atomicAdd(pp + 1, o3);
                }
            }
        }
    }
}

// ---------------- head ----------------
__global__ void head_kernel(const float* __restrict__ lin1W, const float* __restrict__ lin1b,
                            const float* __restrict__ lin2W, const float* __restrict__ lin2b,
                            float* __restrict__ out) {
    __shared__ float sh[H];
    __shared__ float tt[H];
    __shared__ float lg[OUTC];
    int g = blockIdx.x, j = threadIdx.x;
    float c = g_cnt[g];
    if (c < 1.0f) c = 1.0f;
    sh[j] = g_pool[g * H + j] / c;
    __syncthreads();
    float s = lin1b[j];
#pragma unroll 8
    for (int k = 0; k < H; k++) s += sh[k] * lin1W[k * H + j];
    tt[j] = s > 0.f ? s : 0.f;
    __syncthreads();
    if (j < OUTC) {
        float s2 = lin2b[j];
#pragma unroll 8
        for (int k = 0; k < H; k++) s2 += tt[k] * lin2W[k * OUTC + j];
        lg[j] = s2;
    }
    __syncthreads();
    if (j == 0) {
        float m = lg[0];
#pragma unroll
        for (int o = 1; o < OUTC; o++) m = lg[o] > m ? lg[o] : m;
        float se = 0.f;
#pragma unroll
        for (int o = 0; o < OUTC; o++) se += expf(lg[o] - m);
        float l = m + logf(se);
#pragma unroll
        for (int o = 0; o < OUTC; o++) out[g * OUTC + o] = lg[o] - l;
    }
}

// ---------------- launch ----------------
extern "C" void kernel_launch(void* const* d_in, const int* in_sizes, int n_in,
                              void* d_out, int out_size) {
    const float* x      = (const float*)d_in[0];
    const int*   ei     = (const int*)d_in[1];
    const int*   batch  = (const int*)d_in[2];
    const float* c1_W1  = (const float*)d_in[3];
    const float* c1_b1  = (const float*)d_in[4];
    const float* c1_W2  = (const float*)d_in[5];
    const float* c1_b2  = (const float*)d_in[6];
    const float* c1_g   = (const float*)d_in[7];
    const float* c1_be  = (const float*)d_in[8];
    const float* c1_rm  = (const float*)d_in[9];
    const float* c1_rv  = (const float*)d_in[10];
    const float* c1_eps = (const float*)d_in[11];
    const float* Ws1    = (const float*)d_in[12];
    const float* bs1    = (const float*)d_in[13];
    const float* Ws2    = (const float*)d_in[14];
    const float* bs2    = (const float*)d_in[15];
    const float* gs     = (const float*)d_in[16];
    const float* bes    = (const float*)d_in[17];
    const float* rms    = (const float*)d_in[18];
    const float* rvs    = (const float*)d_in[19];
    const float* epss   = (const float*)d_in[20];
    const float* lin1_W = (const float*)d_in[21];
    const float* lin1_b = (const float*)d_in[22];
    const float* lin2_W = (const float*)d_in[23];
    const float* lin2_b = (const float*)d_in[24];
    float* out = (float*)d_out;

    int n = in_sizes[0] / H;
    int e = in_sizes[1] / 2;

    cudaFuncSetAttribute(mlp_mma_kernel, cudaFuncAttributeMaxDynamicSharedMemorySize, DSM);

    const int* src = ei;
    const int* dst = ei + e;

    // device-global buffer addresses (host-side) for ping-pong
    __half* hf0 = nullptr;
    __half* hf1 = nullptr;
    cudaGetSymbolAddress((void**)&hf0, g_hf0);
    cudaGetSymbolAddress((void**)&hf1, g_hf1);

    // setup + CSR build
    zero_kernel<<<(GG * H + 255) / 256, 256>>>(n);
    count_kernel<<<(e + 255) / 256, 256>>>(dst, batch, e, n);
    scan_kernel<<<1, 1024>>>(n);
    fill_kernel<<<(e + 255) / 256, 256>>>(src, dst, e);
    wprep_kernel<<<24, 256>>>(c1_W1, c1_W2, Ws1, Ws2);
    xconv_kernel<<<(n * H / 4 + 255) / 256, 256>>>(x, n * H / 4);

    int mlp_blocks = (n + 127) / 128;

    // layer 1 (agg fused): hf0 -> hf1
    mlp_mma_kernel<<<mlp_blocks, 256, DSM>>>(hf0, hf1, 0, 1, c1_b1, c1_b2,
                                             c1_g, c1_be, c1_rm, c1_rv,
                                             c1_eps, batch, 0, n);
    // layer 2: hf1 -> hf0
    mlp_mma_kernel<<<mlp_blocks, 256, DSM>>>(hf1, hf0, 2, 3, bs1, bs2,
                                             gs, bes, rms, rvs,
                                             epss + 0, batch, 0, n);
    // layer 3 (pools directly): reads hf0
    mlp_mma_kernel<<<mlp_blocks, 256, DSM>>>(hf0, hf1, 4, 5, bs1 + H, bs2 + H,
                                             gs + H, bes + H, rms + H, rvs + H,
                                             epss + 1, batch, 1, n);

    head_kernel<<<GG, H>>>(lin1_W, lin1_b, lin2_W, lin2_b, out);
}

// round 9
// speedup vs baseline: 1.3477x; 1.3477x over previous
#include <cuda_runtime.h>
#include <cuda_bf16.h>
#include <cuda_fp16.h>
#include <stdint.h>

#define NN 50000
#define EE 800000
#define GG 500
#define H 128
#define OUTC 10
#define KS 136                 // padded row stride in f16 elems
#define SB 272                 // row stride bytes
#define IMG (128 * KS * 2)     // 34816 B per 128x128 f16 image
#define DSM (3 * IMG)          // 104448 B dynamic smem: A16, WH, WL

// ---------------- device scratch ----------------
__device__ __align__(16) __half g_hf[NN * H];   // node features (f16)
__device__ __align__(16) __half g_a16[NN * H];  // agg sums rounded to f16 (MLP input)
__device__ int   g_deg[NN];
__device__ int   g_off[NN + 1];
__device__ int   g_cursor[NN];
__device__ int   g_srcs[EE];
__device__ float g_pool[GG * H];
__device__ float g_cnt[GG];
__device__ __align__(16) __half g_wh[6 * 128 * KS];  // weight images (Wt[n][k]) f16 hi
__device__ __align__(16) __half g_wl[6 * 128 * KS];  // f16 lo (residual)

// ---------------- PTX helpers (base ISA only) ----------------
__device__ __forceinline__ uint32_t smem_u32(const void* p) {
    uint32_t a;
    asm("{ .reg .u64 t; cvta.to.shared.u64 t, %1; cvt.u32.u64 %0, t; }" : "=r"(a) : "l"(p));
    return a;
}
#define LDSM4(r0, r1, r2, r3, addr) \
    asm volatile("ldmatrix.sync.aligned.m8n8.x4.shared.b16 {%0,%1,%2,%3}, [%4];" \
                 : "=r"(r0), "=r"(r1), "=r"(r2), "=r"(r3) : "r"(addr))
#define MMA16816(d, a0, a1, a2, a3, b0, b1) \
    asm volatile("mma.sync.aligned.m16n8k16.row.col.f32.f16.f16.f32 " \
                 "{%0,%1,%2,%3}, {%4,%5,%6,%7}, {%8,%9}, {%0,%1,%2,%3};" \
                 : "+f"((d)[0]), "+f"((d)[1]), "+f"((d)[2]), "+f"((d)[3]) \
                 : "r"(a0), "r"(a1), "r"(a2), "r"(a3), "r"(b0), "r"(b1))

// ---------------- setup: zero + counts ----------------
__global__ void zero_kernel(int n) {
    int i = blockIdx.x * blockDim.x + threadIdx.x;
    if (i < n) g_deg[i] = 0;
    if (i < GG * H) g_pool[i] = 0.f;
    if (i < GG) g_cnt[i] = 0.f;
}
__global__ void count_kernel(const int* __restrict__ dst, const int* __restrict__ batch,
                             int e, int n) {
    int i = blockIdx.x * blockDim.x + threadIdx.x;
    if (i < e) atomicAdd(&g_deg[dst[i]], 1);
    if (i < n) atomicAdd(&g_cnt[batch[i]], 1.0f);
}
__global__ void scan_kernel(int n) {
    __shared__ int part[1024];
    int t = threadIdx.x;
    int chunk = (n + 1023) >> 10;
    int start = t * chunk;
    int s = 0;
    for (int i = 0; i < chunk; i++) {
        int idx = start + i;
        if (idx < n) s += g_deg[idx];
    }
    part[t] = s;
    __syncthreads();
    for (int off = 1; off < 1024; off <<= 1) {
        int v = 0;
        if (t >= off) v = part[t - off];
        __syncthreads();
        part[t] += v;
        __syncthreads();
    }
    int base = (t == 0) ? 0 : part[t - 1];
    for (int i = 0; i < chunk; i++) {
        int idx = start + i;
        if (idx < n) {
            g_off[idx] = base;
            g_cursor[idx] = base;
            base += g_deg[idx];
        }
    }
    if (t == 1023) g_off[n] = part[1023];
}
__global__ void fill_kernel(const int* __restrict__ src, const int* __restrict__ dst, int e) {
    int i = blockIdx.x * blockDim.x + threadIdx.x;
    if (i < e) {
        int d = dst[i];
        int p = atomicAdd(&g_cursor[d], 1);
        g_srcs[p] = src[i];
    }
}

// ---------------- x -> f16 convert ----------------
__global__ void xconv_kernel(const float* __restrict__ x, int total4) {
    int i = blockIdx.x * blockDim.x + threadIdx.x;
    if (i < total4) {
        float4 v = ((const float4*)x)[i];
        __half2 h0 = __floats2half2_rn(v.x, v.y);
        __half2 h1 = __floats2half2_rn(v.z, v.w);
        uint2 o;
        o.x = *(unsigned int*)&h0;
        o.y = *(unsigned int*)&h1;
        ((uint2*)g_hf)[i] = o;
    }
}

// ---------------- aggregation: f16 gather, f32 accumulate, f16 store ----------------
__global__ void agg_kernel(const float* __restrict__ eps, int n) {
    int gw = (blockIdx.x * blockDim.x + threadIdx.x) >> 5;
    int lane = threadIdx.x & 31;
    if (gw >= n) return;
    const uint2* in2 = (const uint2*)g_hf;
    float e = 1.0f + *eps;
    uint2 sv = in2[(size_t)gw * 32 + lane];
    float2 f01 = __half22float2(*(__half2*)&sv.x);
    float2 f23 = __half22float2(*(__half2*)&sv.y);
    float4 acc;
    acc.x = f01.x * e; acc.y = f01.y * e; acc.z = f23.x * e; acc.w = f23.y * e;
    int s0 = g_off[gw], s1 = g_off[gw + 1];
    int i = s0;
    for (; i + 3 < s1; i += 4) {
        uint2 va = in2[(size_t)g_srcs[i] * 32 + lane];
        uint2 vb = in2[(size_t)g_srcs[i + 1] * 32 + lane];
        uint2 vc = in2[(size_t)g_srcs[i + 2] * 32 + lane];
        uint2 vd = in2[(size_t)g_srcs[i + 3] * 32 + lane];
        float2 a01 = __half22float2(*(__half2*)&va.x);
        float2 a23 = __half22float2(*(__half2*)&va.y);
        float2 b01 = __half22float2(*(__half2*)&vb.x);
        float2 b23 = __half22float2(*(__half2*)&vb.y);
        float2 c01 = __half22float2(*(__half2*)&vc.x);
        float2 c23 = __half22float2(*(__half2*)&vc.y);
        float2 d01 = __half22float2(*(__half2*)&vd.x);
        float2 d23 = __half22float2(*(__half2*)&vd.y);
        acc.x += (a01.x + b01.x) + (c01.x + d01.x);
        acc.y += (a01.y + b01.y) + (c01.y + d01.y);
        acc.z += (a23.x + b23.x) + (c23.x + d23.x);
        acc.w += (a23.y + b23.y) + (c23.y + d23.y);
    }
    for (; i < s1; i++) {
        uint2 va = in2[(size_t)g_srcs[i] * 32 + lane];
        float2 a01 = __half22float2(*(__half2*)&va.x);
        float2 a23 = __half22float2(*(__half2*)&va.y);
        acc.x += a01.x; acc.y += a01.y; acc.z += a23.x; acc.w += a23.y;
    }
    __half2 o0 = __floats2half2_rn(acc.x, acc.y);
    __half2 o1 = __floats2half2_rn(acc.z, acc.w);
    uint2 o;
    o.x = *(unsigned int*)&o0;
    o.y = *(unsigned int*)&o1;
    ((uint2*)g_a16)[(size_t)gw * 32 + lane] = o;
}

// ---------------- weight prep: Wt[n][k] f16 hi/lo, padded stride ----------------
__global__ void wprep_kernel(const float* __restrict__ c1W1, const float* __restrict__ c1W2,
                             const float* __restrict__ Ws1, const float* __restrict__ Ws2) {
    int m = blockIdx.x >> 2;
    int rg = blockIdx.x & 3;
    const float* W;
    if (m == 0) W = c1W1;
    else if (m == 1) W = c1W2;
    else {
        int l = (m - 2) >> 1;
        W = ((m & 1) == 0) ? (Ws1 + l * H * H) : (Ws2 + l * H * H);
    }
    int tid = threadIdx.x;
    int nrow = rg * 32 + (tid >> 3);
    int kb = (tid & 7) * 16;
    __half* oh = g_wh + m * 128 * KS;
    __half* ol = g_wl + m * 128 * KS;
#pragma unroll
    for (int i = 0; i < 8; i++) {
        int k = kb + 2 * i;
        float v0 = W[k * H + nrow];
        float v1 = W[(k + 1) * H + nrow];
        __half2 h2 = __floats2half2_rn(v0, v1);
        float2 hf = __half22float2(h2);
        __half2 l2 = __floats2half2_rn(v0 - hf.x, v1 - hf.y);
        *(__half2*)(oh + nrow * KS + k) = h2;
        *(__half2*)(ol + nrow * KS + k) = l2;
    }
}

// ---------------- MLP on mma.sync (f16 A, f16 hi/lo W split), 2 CTAs/SM ----------------
__device__ __forceinline__ void copy_w(char* WH, char* WL, int wi, int tid) {
    const uint4* s1 = (const uint4*)(g_wh + (size_t)wi * 128 * KS);
    const uint4* s2 = (const uint4*)(g_wl + (size_t)wi * 128 * KS);
    uint4* d1 = (uint4*)WH;
    uint4* d2 = (uint4*)WL;
    for (int j = tid; j < IMG / 16; j += 256) {
        d1[j] = s1[j];
        d2[j] = s2[j];
    }
}

__global__ __launch_bounds__(256, 2) void mlp_mma_kernel(
    int w1i, int w2i,
    const float* __restrict__ b1, const float* __restrict__ b2,
    const float* __restrict__ gam, const float* __restrict__ bet,
    const float* __restrict__ rm, const float* __restrict__ rv,
    const int* __restrict__ batchv, int lastlayer, int n) {
    extern __shared__ char dsm[];
    __shared__ float s_b1[H], s_b2[H], s_sc[H], s_sf[H];

    char* A16 = dsm;
    char* WH = dsm + 1 * IMG;
    char* WL = dsm + 2 * IMG;

    int tid = threadIdx.x, wid = tid >> 5, lane = tid & 31;
    int wm = wid >> 1, wn = wid & 1;        // 4x2 warp grid; warp tile 32(m) x 64(n)
    int qg = lane >> 2, qt = lane & 3;      // quad group / thread

    if (tid < H) {
        s_b1[tid] = b1[tid];
        s_b2[tid] = b2[tid];
        float sc = gam[tid] * rsqrtf(rv[tid] + 1e-5f);
        s_sc[tid] = sc;
        s_sf[tid] = bet[tid] - rm[tid] * sc;
    }
    copy_w(WH, WL, w1i, tid);

    // build A image (straight f16 copy, padded stride)
    int row0 = blockIdx.x * 128;
    {
        int r = tid >> 1, cb0 = (tid & 1) * 64;
        int grow = row0 + r;
        uint4* drow = (uint4*)(A16 + r * SB + cb0 * 2);
        if (grow < n) {
            const uint4* srow = (const uint4*)(g_a16 + (size_t)grow * H + cb0);
#pragma unroll
            for (int i = 0; i < 8; i++) drow[i] = srow[i];
        } else {
            uint4 z = make_uint4(0, 0, 0, 0);
#pragma unroll
            for (int i = 0; i < 8; i++) drow[i] = z;
        }
    }
    __syncthreads();

    // per-lane ldmatrix address offsets
    uint32_t aA16 = smem_u32(A16);
    uint32_t aWH = smem_u32(WH), aWL = smem_u32(WL);
    uint32_t a_loff = (uint32_t)((wm * 32 + (lane & 15)) * SB + (lane >> 4) * 16);
    uint32_t b_row = (uint32_t)((lane & 7) | ((lane & 16) >> 1));
    uint32_t b_loff = (uint32_t)((wn * 64) * SB) + b_row * SB + (((uint32_t)lane >> 3) & 1) * 16;

    float acc[2][8][4];

    for (int pass = 0; pass < 2; pass++) {
#pragma unroll
        for (int mf = 0; mf < 2; mf++)
#pragma unroll
            for (int nf = 0; nf < 8; nf++)
#pragma unroll
                for (int q = 0; q < 4; q++) acc[mf][nf][q] = 0.f;

#pragma unroll
        for (int ks = 0; ks < 8; ks++) {
            uint32_t a0, a1, a2, a3, a4, a5, a6, a7;
            uint32_t abase = aA16 + a_loff + (uint32_t)(ks * 32);
            LDSM4(a0, a1, a2, a3, abase);
            LDSM4(a4, a5, a6, a7, abase + 16u * SB);
#pragma unroll
            for (int prod = 0; prod < 2; prod++) {
                uint32_t wb = prod ? aWL : aWH;
#pragma unroll
                for (int g2 = 0; g2 < 4; g2++) {
                    uint32_t b0, b1x, b2, b3;
                    uint32_t bbase = wb + b_loff + (uint32_t)(g2 * 16 * SB + ks * 32);
                    LDSM4(b0, b1x, b2, b3, bbase);
                    MMA16816(acc[0][2 * g2],     a0, a1, a2, a3, b0, b1x);
                    MMA16816(acc[0][2 * g2 + 1], a0, a1, a2, a3, b2, b3);
                    MMA16816(acc[1][2 * g2],     a4, a5, a6, a7, b0, b1x);
                    MMA16816(acc[1][2 * g2 + 1], a4, a5, a6, a7, b2, b3);
                }
            }
        }

        if (pass == 0) {
            // all pass-0 reads of A16/WH/WL done
            __syncthreads();
            // epilogue 1: bias + relu -> rebuild A image (f16); stage W2 in its shadow
#pragma unroll
            for (int mf = 0; mf < 2; mf++) {
                int rA = wm * 32 + mf * 16 + qg;
#pragma unroll
                for (int nf = 0; nf < 8; nf++) {
                    int c = wn * 64 + nf * 8 + 2 * qt;
                    float v0 = fmaxf(acc[mf][nf][0] + s_b1[c], 0.f);
                    float v1 = fmaxf(acc[mf][nf][1] + s_b1[c + 1], 0.f);
                    float v2 = fmaxf(acc[mf][nf][2] + s_b1[c], 0.f);
                    float v3 = fmaxf(acc[mf][nf][3] + s_b1[c + 1], 0.f);
                    *(__half2*)(A16 + rA * SB + c * 2)       = __floats2half2_rn(v0, v1);
                    *(__half2*)(A16 + (rA + 8) * SB + c * 2) = __floats2half2_rn(v2, v3);
                }
            }
            copy_w(WH, WL, w2i, tid);
            __syncthreads();
        }
    }

    // epilogue 2: bias + relu + BN -> g_hf f16 (or atomic pool on last layer)
#pragma unroll
    for (int mf = 0; mf < 2; mf++) {
        int rA = wm * 32 + mf * 16 + qg;
        int growA = row0 + rA, growB = growA + 8;
#pragma unroll
        for (int nf = 0; nf < 8; nf++) {
            int c = wn * 64 + nf * 8 + 2 * qt;
            float o0 = fmaxf(acc[mf][nf][0] + s_b2[c], 0.f)     * s_sc[c]     + s_sf[c];
            float o1 = fmaxf(acc[mf][nf][1] + s_b2[c + 1], 0.f) * s_sc[c + 1] + s_sf[c + 1];
            float o2 = fmaxf(acc[mf][nf][2] + s_b2[c], 0.f)     * s_sc[c]     + s_sf[c];
            float o3 = fmaxf(acc[mf][nf][3] + s_b2[c + 1], 0.f) * s_sc[c + 1] + s_sf[c + 1];
            if (!lastlayer) {
                if (growA < n) *(__half2*)&g_hf[(size_t)growA * H + c] = __floats2half2_rn(o0, o1);
                if (growB < n) *(__half2*)&g_hf[(size_t)growB * H + c] = __floats2half2_rn(o2, o3);
            } else {
                if (growA < n) {
                    float* pp = g_pool + (size_t)batchv[growA] * H + c;
                    atomicAdd(pp, o0);
                    atomicAdd(pp + 1, o1);
                }
                if (growB < n) {
                    float* pp = g_pool + (size_t)batchv[growB] * H + c;
                    atomicAdd(pp, o2);
                    atomicAdd(pp + 1, o3);
                }
            }
        }
    }
}

// ---------------- head ----------------
__global__ void head_kernel(const float* __restrict__ lin1W, const float* __restrict__ lin1b,
                            const float* __restrict__ lin2W, const float* __restrict__ lin2b,
                            float* __restrict__ out) {
    __shared__ float sh[H];
    __shared__ float tt[H];
    __shared__ float lg[OUTC];
    int g = blockIdx.x, j = threadIdx.x;
    float c = g_cnt[g];
    if (c < 1.0f) c = 1.0f;
    sh[j] = g_pool[g * H + j] / c;
    __syncthreads();
    float s = lin1b[j];
#pragma unroll 8
    for (int k = 0; k < H; k++) s += sh[k] * lin1W[k * H + j];
    tt[j] = s > 0.f ? s : 0.f;
    __syncthreads();
    if (j < OUTC) {
        float s2 = lin2b[j];
#pragma unroll 8
        for (int k = 0; k < H; k++) s2 += tt[k] * lin2W[k * OUTC + j];
        lg[j] = s2;
    }
    __syncthreads();
    if (j == 0) {
        float m = lg[0];
#pragma unroll
        for (int o = 1; o < OUTC; o++) m = lg[o] > m ? lg[o] : m;
        float se = 0.f;
#pragma unroll
        for (int o = 0; o < OUTC; o++) se += expf(lg[o] - m);
        float l = m + logf(se);
#pragma unroll
        for (int o = 0; o < OUTC; o++) out[g * OUTC + o] = lg[o] - l;
    }
}

// ---------------- launch ----------------
extern "C" void kernel_launch(void* const* d_in, const int* in_sizes, int n_in,
                              void* d_out, int out_size) {
    const float* x      = (const float*)d_in[0];
    const int*   ei     = (const int*)d_in[1];
    const int*   batch  = (const int*)d_in[2];
    const float* c1_W1  = (const float*)d_in[3];
    const float* c1_b1  = (const float*)d_in[4];
    const float* c1_W2  = (const float*)d_in[5];
    const float* c1_b2  = (const float*)d_in[6];
    const float* c1_g   = (const float*)d_in[7];
    const float* c1_be  = (const float*)d_in[8];
    const float* c1_rm  = (const float*)d_in[9];
    const float* c1_rv  = (const float*)d_in[10];
    const float* c1_eps = (const float*)d_in[11];
    const float* Ws1    = (const float*)d_in[12];
    const float* bs1    = (const float*)d_in[13];
    const float* Ws2    = (const float*)d_in[14];
    const float* bs2    = (const float*)d_in[15];
    const float* gs     = (const float*)d_in[16];
    const float* bes    = (const float*)d_in[17];
    const float* rms    = (const float*)d_in[18];
    const float* rvs    = (const float*)d_in[19];
    const float* epss   = (const float*)d_in[20];
    const float* lin1_W = (const float*)d_in[21];
    const float* lin1_b = (const float*)d_in[22];
    const float* lin2_W = (const float*)d_in[23];
    const float* lin2_b = (const float*)d_in[24];
    float* out = (float*)d_out;

    int n = in_sizes[0] / H;
    int e = in_sizes[1] / 2;

    cudaFuncSetAttribute(mlp_mma_kernel, cudaFuncAttributeMaxDynamicSharedMemorySize, DSM);

    const int* src = ei;
    const int* dst = ei + e;

    // setup + CSR build
    zero_kernel<<<(GG * H + 255) / 256, 256>>>(n);
    count_kernel<<<(e + 255) / 256, 256>>>(dst, batch, e, n);
    scan_kernel<<<1, 1024>>>(n);
    fill_kernel<<<(e + 255) / 256, 256>>>(src, dst, e);
    wprep_kernel<<<24, 256>>>(c1_W1, c1_W2, Ws1, Ws2);
    xconv_kernel<<<(n * H / 4 + 255) / 256, 256>>>(x, n * H / 4);

    int agg_blocks = (n * 32 + 255) / 256;
    int mlp_blocks = (n + 127) / 128;

    // layer 1
    agg_kernel<<<agg_blocks, 256>>>(c1_eps, n);
    mlp_mma_kernel<<<mlp_blocks, 256, DSM>>>(0, 1, c1_b1, c1_b2,
                                             c1_g, c1_be, c1_rm, c1_rv,
                                             batch, 0, n);
    // layer 2
    agg_kernel<<<agg_blocks, 256>>>(epss + 0, n);
    mlp_mma_kernel<<<mlp_blocks, 256, DSM>>>(2, 3, bs1, bs2,
                                             gs, bes, rms, rvs,
                                             batch, 0, n);
    // layer 3 (pools directly)
    agg_kernel<<<agg_blocks, 256>>>(epss + 1, n);
    mlp_mma_kernel<<<mlp_blocks, 256, DSM>>>(4, 5, bs1 + H, bs2 + H,
                                             gs + H, bes + H, rms + H, rvs + H,
                                             batch, 1, n);

    head_kernel<<<GG, H>>>(lin1_W, lin1_b, lin2_W, lin2_b, out);
}

// round 10
// speedup vs baseline: 1.4013x; 1.0398x over previous
#include <cuda_runtime.h>
#include <cuda_bf16.h>
#include <cuda_fp16.h>
#include <stdint.h>

#define NN 50000
#define EE 800000
#define GG 500
#define H 128
#define OUTC 10
#define KS 136                 // padded row stride in f16 elems
#define SB 272                 // row stride bytes
#define IMG (128 * KS * 2)     // 34816 B per 128x128 f16 image
#define DSM (5 * IMG)          // 174080 B dynamic smem: A16, W1H, W1L, W2H, W2L
#define MLP_GRID 148

// ---------------- device scratch ----------------
__device__ __align__(16) __half g_hf[NN * H];   // node features (f16)
__device__ __align__(16) __half g_a16[NN * H];  // agg sums rounded to f16 (MLP input)
__device__ int   g_deg[NN];
__device__ int   g_off[NN + 1];
__device__ int   g_cursor[NN];
__device__ int   g_srcs[EE];
__device__ float g_pool[GG * H];
__device__ float g_cnt[GG];
__device__ __align__(16) __half g_wh[6 * 128 * KS];  // weight images (Wt[n][k]) f16 hi
__device__ __align__(16) __half g_wl[6 * 128 * KS];  // f16 lo (residual)

// ---------------- PTX helpers (base ISA only) ----------------
__device__ __forceinline__ uint32_t smem_u32(const void* p) {
    uint32_t a;
    asm("{ .reg .u64 t; cvta.to.shared.u64 t, %1; cvt.u32.u64 %0, t; }" : "=r"(a) : "l"(p));
    return a;
}
#define LDSM4(r0, r1, r2, r3, addr) \
    asm volatile("ldmatrix.sync.aligned.m8n8.x4.shared.b16 {%0,%1,%2,%3}, [%4];" \
                 : "=r"(r0), "=r"(r1), "=r"(r2), "=r"(r3) : "r"(addr))
#define MMA16816(d, a0, a1, a2, a3, b0, b1) \
    asm volatile("mma.sync.aligned.m16n8k16.row.col.f32.f16.f16.f32 " \
                 "{%0,%1,%2,%3}, {%4,%5,%6,%7}, {%8,%9}, {%0,%1,%2,%3};" \
                 : "+f"((d)[0]), "+f"((d)[1]), "+f"((d)[2]), "+f"((d)[3]) \
                 : "r"(a0), "r"(a1), "r"(a2), "r"(a3), "r"(b0), "r"(b1))

// ---------------- setup: zero + counts ----------------
__global__ void zero_kernel(int n) {
    int i = blockIdx.x * blockDim.x + threadIdx.x;
    if (i < n) g_deg[i] = 0;
    if (i < GG * H) g_pool[i] = 0.f;
    if (i < GG) g_cnt[i] = 0.f;
}
__global__ void count_kernel(const int* __restrict__ dst, const int* __restrict__ batch,
                             int e, int n) {
    int i = blockIdx.x * blockDim.x + threadIdx.x;
    if (i < e) atomicAdd(&g_deg[dst[i]], 1);
    if (i < n) atomicAdd(&g_cnt[batch[i]], 1.0f);
}
__global__ void scan_kernel(int n) {
    __shared__ int part[1024];
    int t = threadIdx.x;
    int chunk = (n + 1023) >> 10;
    int start = t * chunk;
    int s = 0;
    for (int i = 0; i < chunk; i++) {
        int idx = start + i;
        if (idx < n) s += g_deg[idx];
    }
    part[t] = s;
    __syncthreads();
    for (int off = 1; off < 1024; off <<= 1) {
        int v = 0;
        if (t >= off) v = part[t - off];
        __syncthreads();
        part[t] += v;
        __syncthreads();
    }
    int base = (t == 0) ? 0 : part[t - 1];
    for (int i = 0; i < chunk; i++) {
        int idx = start + i;
        if (idx < n) {
            g_off[idx] = base;
            g_cursor[idx] = base;
            base += g_deg[idx];
        }
    }
    if (t == 1023) g_off[n] = part[1023];
}
__global__ void fill_kernel(const int* __restrict__ src, const int* __restrict__ dst, int e) {
    int i = blockIdx.x * blockDim.x + threadIdx.x;
    if (i < e) {
        int d = dst[i];
        int p = atomicAdd(&g_cursor[d], 1);
        g_srcs[p] = src[i];
    }
}

// ---------------- x -> f16 convert ----------------
__global__ void xconv_kernel(const float* __restrict__ x, int total4) {
    int i = blockIdx.x * blockDim.x + threadIdx.x;
    if (i < total4) {
        float4 v = ((const float4*)x)[i];
        __half2 h0 = __floats2half2_rn(v.x, v.y);
        __half2 h1 = __floats2half2_rn(v.z, v.w);
        uint2 o;
        o.x = *(unsigned int*)&h0;
        o.y = *(unsigned int*)&h1;
        ((uint2*)g_hf)[i] = o;
    }
}

// ---------------- aggregation: f16 gather, f32 accumulate, f16 store ----------------
__global__ void agg_kernel(const float* __restrict__ eps, int n) {
    int gw = (blockIdx.x * blockDim.x + threadIdx.x) >> 5;
    int lane = threadIdx.x & 31;
    if (gw >= n) return;
    const uint2* in2 = (const uint2*)g_hf;
    float e = 1.0f + *eps;
    uint2 sv = in2[(size_t)gw * 32 + lane];
    float2 f01 = __half22float2(*(__half2*)&sv.x);
    float2 f23 = __half22float2(*(__half2*)&sv.y);
    float4 acc;
    acc.x = f01.x * e; acc.y = f01.y * e; acc.z = f23.x * e; acc.w = f23.y * e;
    int s0 = g_off[gw], s1 = g_off[gw + 1];
    int i = s0;
    for (; i + 3 < s1; i += 4) {
        uint2 va = in2[(size_t)g_srcs[i] * 32 + lane];
        uint2 vb = in2[(size_t)g_srcs[i + 1] * 32 + lane];
        uint2 vc = in2[(size_t)g_srcs[i + 2] * 32 + lane];
        uint2 vd = in2[(size_t)g_srcs[i + 3] * 32 + lane];
        float2 a01 = __half22float2(*(__half2*)&va.x);
        float2 a23 = __half22float2(*(__half2*)&va.y);
        float2 b01 = __half22float2(*(__half2*)&vb.x);
        float2 b23 = __half22float2(*(__half2*)&vb.y);
        float2 c01 = __half22float2(*(__half2*)&vc.x);
        float2 c23 = __half22float2(*(__half2*)&vc.y);
        float2 d01 = __half22float2(*(__half2*)&vd.x);
        float2 d23 = __half22float2(*(__half2*)&vd.y);
        acc.x += (a01.x + b01.x) + (c01.x + d01.x);
        acc.y += (a01.y + b01.y) + (c01.y + d01.y);
        acc.z += (a23.x + b23.x) + (c23.x + d23.x);
        acc.w += (a23.y + b23.y) + (c23.y + d23.y);
    }
    for (; i < s1; i++) {
        uint2 va = in2[(size_t)g_srcs[i] * 32 + lane];
        float2 a01 = __half22float2(*(__half2*)&va.x);
        float2 a23 = __half22float2(*(__half2*)&va.y);
        acc.x += a01.x; acc.y += a01.y; acc.z += a23.x; acc.w += a23.y;
    }
    __half2 o0 = __floats2half2_rn(acc.x, acc.y);
    __half2 o1 = __floats2half2_rn(acc.z, acc.w);
    uint2 o;
    o.x = *(unsigned int*)&o0;
    o.y = *(unsigned int*)&o1;
    ((uint2*)g_a16)[(size_t)gw * 32 + lane] = o;
}

// ---------------- weight prep: Wt[n][k] f16 hi/lo, padded stride ----------------
__global__ void wprep_kernel(const float* __restrict__ c1W1, const float* __restrict__ c1W2,
                             const float* __restrict__ Ws1, const float* __restrict__ Ws2) {
    int m = blockIdx.x >> 2;
    int rg = blockIdx.x & 3;
    const float* W;
    if (m == 0) W = c1W1;
    else if (m == 1) W = c1W2;
    else {
        int l = (m - 2) >> 1;
        W = ((m & 1) == 0) ? (Ws1 + l * H * H) : (Ws2 + l * H * H);
    }
    int tid = threadIdx.x;
    int nrow = rg * 32 + (tid >> 3);
    int kb = (tid & 7) * 16;
    __half* oh = g_wh + m * 128 * KS;
    __half* ol = g_wl + m * 128 * KS;
#pragma unroll
    for (int i = 0; i < 8; i++) {
        int k = kb + 2 * i;
        float v0 = W[k * H + nrow];
        float v1 = W[(k + 1) * H + nrow];
        __half2 h2 = __floats2half2_rn(v0, v1);
        float2 hf = __half22float2(h2);
        __half2 l2 = __floats2half2_rn(v0 - hf.x, v1 - hf.y);
        *(__half2*)(oh + nrow * KS + k) = h2;
        *(__half2*)(ol + nrow * KS + k) = l2;
    }
}

// ---------------- MLP on mma.sync, persistent multi-tile CTAs ----------------
__device__ __forceinline__ void copy_w(char* WH, char* WL, int wi, int tid) {
    const uint4* s1 = (const uint4*)(g_wh + (size_t)wi * 128 * KS);
    const uint4* s2 = (const uint4*)(g_wl + (size_t)wi * 128 * KS);
    uint4* d1 = (uint4*)WH;
    uint4* d2 = (uint4*)WL;
    for (int j = tid; j < IMG / 16; j += 256) {
        d1[j] = s1[j];
        d2[j] = s2[j];
    }
}

__global__ __launch_bounds__(256, 1) void mlp_mma_kernel(
    int w1i, int w2i,
    const float* __restrict__ b1, const float* __restrict__ b2,
    const float* __restrict__ gam, const float* __restrict__ bet,
    const float* __restrict__ rm, const float* __restrict__ rv,
    const int* __restrict__ batchv, int lastlayer, int n, int ntiles) {
    extern __shared__ char dsm[];
    __shared__ float s_b1[H], s_b2[H], s_sc[H], s_sf[H];

    char* A16 = dsm;
    char* W1H = dsm + 1 * IMG;
    char* W1L = dsm + 2 * IMG;
    char* W2H = dsm + 3 * IMG;
    char* W2L = dsm + 4 * IMG;

    int tid = threadIdx.x, wid = tid >> 5, lane = tid & 31;
    int wm = wid >> 1, wn = wid & 1;        // 4x2 warp grid; warp tile 32(m) x 64(n)
    int qg = lane >> 2, qt = lane & 3;      // quad group / thread

    // ---- one-time prologue: constants + all four weight images ----
    if (tid < H) {
        s_b1[tid] = b1[tid];
        s_b2[tid] = b2[tid];
        float sc = gam[tid] * rsqrtf(rv[tid] + 1e-5f);
        s_sc[tid] = sc;
        s_sf[tid] = bet[tid] - rm[tid] * sc;
    }
    copy_w(W1H, W1L, w1i, tid);
    copy_w(W2H, W2L, w2i, tid);

    // per-lane ldmatrix address offsets (tile-invariant)
    uint32_t aA16 = smem_u32(A16);
    uint32_t aW1H = smem_u32(W1H), aW1L = smem_u32(W1L);
    uint32_t aW2H = smem_u32(W2H), aW2L = smem_u32(W2L);
    uint32_t a_loff = (uint32_t)((wm * 32 + (lane & 15)) * SB + (lane >> 4) * 16);
    uint32_t b_row = (uint32_t)((lane & 7) | ((lane & 16) >> 1));
    uint32_t b_loff = (uint32_t)((wn * 64) * SB) + b_row * SB + (((uint32_t)lane >> 3) & 1) * 16;

    float acc[2][8][4];

    for (int tile = blockIdx.x; tile < ntiles; tile += MLP_GRID) {
        int row0 = tile * 128;

        // build A image (straight f16 copy, padded stride)
        {
            int r = tid >> 1, cb0 = (tid & 1) * 64;
            int grow = row0 + r;
            uint4* drow = (uint4*)(A16 + r * SB + cb0 * 2);
            if (grow < n) {
                const uint4* srow = (const uint4*)(g_a16 + (size_t)grow * H + cb0);
#pragma unroll
                for (int i = 0; i < 8; i++) drow[i] = srow[i];
            } else {
                uint4 z = make_uint4(0, 0, 0, 0);
#pragma unroll
                for (int i = 0; i < 8; i++) drow[i] = z;
            }
        }
        __syncthreads();

        for (int pass = 0; pass < 2; pass++) {
            uint32_t wHI = pass ? aW2H : aW1H;
            uint32_t wLO = pass ? aW2L : aW1L;
#pragma unroll
            for (int mf = 0; mf < 2; mf++)
#pragma unroll
                for (int nf = 0; nf < 8; nf++)
#pragma unroll
                    for (int q = 0; q < 4; q++) acc[mf][nf][q] = 0.f;

#pragma unroll
            for (int ks = 0; ks < 8; ks++) {
                uint32_t a0, a1, a2, a3, a4, a5, a6, a7;
                uint32_t abase = aA16 + a_loff + (uint32_t)(ks * 32);
                LDSM4(a0, a1, a2, a3, abase);
                LDSM4(a4, a5, a6, a7, abase + 16u * SB);
#pragma unroll
                for (int prod = 0; prod < 2; prod++) {
                    uint32_t wb = prod ? wLO : wHI;
#pragma unroll
                    for (int g2 = 0; g2 < 4; g2++) {
                        uint32_t b0, b1x, b2, b3;
                        uint32_t bbase = wb + b_loff + (uint32_t)(g2 * 16 * SB + ks * 32);
                        LDSM4(b0, b1x, b2, b3, bbase);
                        MMA16816(acc[0][2 * g2],     a0, a1, a2, a3, b0, b1x);
                        MMA16816(acc[0][2 * g2 + 1], a0, a1, a2, a3, b2, b3);
                        MMA16816(acc[1][2 * g2],     a4, a5, a6, a7, b0, b1x);
                        MMA16816(acc[1][2 * g2 + 1], a4, a5, a6, a7, b2, b3);
                    }
                }
            }

            if (pass == 0) {
                __syncthreads();   // pass-0 A reads complete
                // epilogue 1: bias + relu -> rebuild A image (f16)
#pragma unroll
                for (int mf = 0; mf < 2; mf++) {
                    int rA = wm * 32 + mf * 16 + qg;
#pragma unroll
                    for (int nf = 0; nf < 8; nf++) {
                        int c = wn * 64 + nf * 8 + 2 * qt;
                        float v0 = fmaxf(acc[mf][nf][0] + s_b1[c], 0.f);
                        float v1 = fmaxf(acc[mf][nf][1] + s_b1[c + 1], 0.f);
                        float v2 = fmaxf(acc[mf][nf][2] + s_b1[c], 0.f);
                        float v3 = fmaxf(acc[mf][nf][3] + s_b1[c + 1], 0.f);
                        *(__half2*)(A16 + rA * SB + c * 2)       = __floats2half2_rn(v0, v1);
                        *(__half2*)(A16 + (rA + 8) * SB + c * 2) = __floats2half2_rn(v2, v3);
                    }
                }
                __syncthreads();
            }
        }

        // epilogue 2: bias + relu + BN -> g_hf f16 (or atomic pool on last layer)
#pragma unroll
        for (int mf = 0; mf < 2; mf++) {
            int rA = wm * 32 + mf * 16 + qg;
            int growA = row0 + rA, growB = growA + 8;
#pragma unroll
            for (int nf = 0; nf < 8; nf++) {
                int c = wn * 64 + nf * 8 + 2 * qt;
                float o0 = fmaxf(acc[mf][nf][0] + s_b2[c], 0.f)     * s_sc[c]     + s_sf[c];
                float o1 = fmaxf(acc[mf][nf][1] + s_b2[c + 1], 0.f) * s_sc[c + 1] + s_sf[c + 1];
                float o2 = fmaxf(acc[mf][nf][2] + s_b2[c], 0.f)     * s_sc[c]     + s_sf[c];
                float o3 = fmaxf(acc[mf][nf][3] + s_b2[c + 1], 0.f) * s_sc[c + 1] + s_sf[c + 1];
                if (!lastlayer) {
                    if (growA < n) *(__half2*)&g_hf[(size_t)growA * H + c] = __floats2half2_rn(o0, o1);
                    if (growB < n) *(__half2*)&g_hf[(size_t)growB * H + c] = __floats2half2_rn(o2, o3);
                } else {
                    if (growA < n) {
                        float* pp = g_pool + (size_t)batchv[growA] * H + c;
                        atomicAdd(pp, o0);
                        atomicAdd(pp + 1, o1);
                    }
                    if (growB < n) {
                        float* pp = g_pool + (size_t)batchv[growB] * H + c;
                        atomicAdd(pp, o2);
                        atomicAdd(pp + 1, o3);
                    }
                }
            }
        }
        __syncthreads();   // pass-1 A reads done before next tile's A build
    }
}

// ---------------- head ----------------
__global__ void head_kernel(const float* __restrict__ lin1W, const float* __restrict__ lin1b,
                            const float* __restrict__ lin2W, const float* __restrict__ lin2b,
                            float* __restrict__ out) {
    __shared__ float sh[H];
    __shared__ float tt[H];
    __shared__ float lg[OUTC];
    int g = blockIdx.x, j = threadIdx.x;
    float c = g_cnt[g];
    if (c < 1.0f) c = 1.0f;
    sh[j] = g_pool[g * H + j] / c;
    __syncthreads();
    float s = lin1b[j];
#pragma unroll 8
    for (int k = 0; k < H; k++) s += sh[k] * lin1W[k * H + j];
    tt[j] = s > 0.f ? s : 0.f;
    __syncthreads();
    if (j < OUTC) {
        float s2 = lin2b[j];
#pragma unroll 8
        for (int k = 0; k < H; k++) s2 += tt[k] * lin2W[k * OUTC + j];
        lg[j] = s2;
    }
    __syncthreads();
    if (j == 0) {
        float m = lg[0];
#pragma unroll
        for (int o = 1; o < OUTC; o++) m = lg[o] > m ? lg[o] : m;
        float se = 0.f;
#pragma unroll
        for (int o = 0; o < OUTC; o++) se += expf(lg[o] - m);
        float l = m + logf(se);
#pragma unroll
        for (int o = 0; o < OUTC; o++) out[g * OUTC + o] = lg[o] - l;
    }
}

// ---------------- launch ----------------
extern "C" void kernel_launch(void* const* d_in, const int* in_sizes, int n_in,
                              void* d_out, int out_size) {
    const float* x      = (const float*)d_in[0];
    const int*   ei     = (const int*)d_in[1];
    const int*   batch  = (const int*)d_in[2];
    const float* c1_W1  = (const float*)d_in[3];
    const float* c1_b1  = (const float*)d_in[4];
    const float* c1_W2  = (const float*)d_in[5];
    const float* c1_b2  = (const float*)d_in[6];
    const float* c1_g   = (const float*)d_in[7];
    const float* c1_be  = (const float*)d_in[8];
    const float* c1_rm  = (const float*)d_in[9];
    const float* c1_rv  = (const float*)d_in[10];
    const float* c1_eps = (const float*)d_in[11];
    const float* Ws1    = (const float*)d_in[12];
    const float* bs1    = (const float*)d_in[13];
    const float* Ws2    = (const float*)d_in[14];
    const float* bs2    = (const float*)d_in[15];
    const float* gs     = (const float*)d_in[16];
    const float* bes    = (const float*)d_in[17];
    const float* rms    = (const float*)d_in[18];
    const float* rvs    = (const float*)d_in[19];
    const float* epss   = (const float*)d_in[20];
    const float* lin1_W = (const float*)d_in[21];
    const float* lin1_b = (const float*)d_in[22];
    const float* lin2_W = (const float*)d_in[23];
    const float* lin2_b = (const float*)d_in[24];
    float* out = (float*)d_out;

    int n = in_sizes[0] / H;
    int e = in_sizes[1] / 2;
    int ntiles = (n + 127) / 128;

    cudaFuncSetAttribute(mlp_mma_kernel, cudaFuncAttributeMaxDynamicSharedMemorySize, DSM);

    const int* src = ei;
    const int* dst = ei + e;

    // setup + CSR build
    zero_kernel<<<(GG * H + 255) / 256, 256>>>(n);
    count_kernel<<<(e + 255) / 256, 256>>>(dst, batch, e, n);
    scan_kernel<<<1, 1024>>>(n);
    fill_kernel<<<(e + 255) / 256, 256>>>(src, dst, e);
    wprep_kernel<<<24, 256>>>(c1_W1, c1_W2, Ws1, Ws2);
    xconv_kernel<<<(n * H / 4 + 255) / 256, 256>>>(x, n * H / 4);

    int agg_blocks = (n * 32 + 255) / 256;

    // layer 1
    agg_kernel<<<agg_blocks, 256>>>(c1_eps, n);
    mlp_mma_kernel<<<MLP_GRID, 256, DSM>>>(0, 1, c1_b1, c1_b2,
                                           c1_g, c1_be, c1_rm, c1_rv,
                                           batch, 0, n, ntiles);
    // layer 2
    agg_kernel<<<agg_blocks, 256>>>(epss + 0, n);
    mlp_mma_kernel<<<MLP_GRID, 256, DSM>>>(2, 3, bs1, bs2,
                                           gs, bes, rms, rvs,
                                           batch, 0, n, ntiles);
    // layer 3 (pools directly)
    agg_kernel<<<agg_blocks, 256>>>(epss + 1, n);
    mlp_mma_kernel<<<MLP_GRID, 256, DSM>>>(4, 5, bs1 + H, bs2 + H,
                                           gs + H, bes + H, rms + H, rvs + H,
                                           batch, 1, n, ntiles);

    head_kernel<<<GG, H>>>(lin1_W, lin1_b, lin2_W, lin2_b, out);
}